// round 13
// baseline (speedup 1.0000x reference)
#include <cuda_runtime.h>
#include <cuda_bf16.h>
#include <cstdint>

#define B_SZ 1024
#define C_SZ 128
#define ELL 16
#define EQ 3
#define E_SZ 10
#define P3 23
#define P2 5
#define OUT_STRIDE 384
#define MROWS 48           // (w,xx) rows, m = w*16 + xx
#define KTOT 160           // 128 quad + 8 cross + 16 lin + 1 const + 7 pad
#define KPAIR 80
#define KW 29              // 23 + 5 + 1 weight slots
#define NT 32              // b-tile
#define GSZ (MROWS * KTOT) // 7680
#define LDA 84             // smem pair-stride (21 x 16B, LDSM conflict-free)
#define XSW 17             // xs row stride (floats)
#define NROW (B_SZ * C_SZ) // 131072 z rows

__device__ int g_order[B_SZ];
__device__ int g_bstart[E_SZ + 1];
__device__ __align__(16) float g_AbigT[KW * GSZ];
__device__ __align__(16) __nv_bfloat16 g_Ghi[E_SZ * C_SZ * GSZ];
__device__ __align__(16) __nv_bfloat16 g_Glo[E_SZ * C_SZ * GSZ];
__device__ __align__(16) uint32_t g_Zh[(size_t)NROW * KPAIR];  // 42 MB
__device__ __align__(16) uint32_t g_Zl[(size_t)NROW * KPAIR];  // 42 MB

// ---- packed f32x2 helpers ----
static __device__ __forceinline__ unsigned long long pack2(float lo, float hi) {
    unsigned long long r;
    asm("mov.b64 %0, {%1, %2};" : "=l"(r) : "f"(lo), "f"(hi));
    return r;
}
static __device__ __forceinline__ void unpack2(float& lo, float& hi, unsigned long long v) {
    asm("mov.b64 {%0, %1}, %2;" : "=f"(lo), "=f"(hi) : "l"(v));
}
static __device__ __forceinline__ unsigned long long fma2(unsigned long long a,
                                                          unsigned long long b,
                                                          unsigned long long c) {
    unsigned long long d;
    asm("fma.rn.f32x2 %0, %1, %2, %3;" : "=l"(d) : "l"(a), "l"(b), "l"(c));
    return d;
}

// truncation split: hi = top-16-bits (exact), lo = RN-bf16 of remainder
static __device__ __forceinline__ uint32_t tsplit(float z0, float z1, uint32_t& lo) {
    uint32_t u0 = __float_as_uint(z0), u1 = __float_as_uint(z1);
    float l0 = z0 - __uint_as_float(u0 & 0xFFFF0000u);
    float l1 = z1 - __uint_as_float(u1 & 0xFFFF0000u);
    uint32_t hi;
    asm("prmt.b32 %0, %1, %2, 0x7632;" : "=r"(hi) : "r"(u0), "r"(u1));
    asm("cvt.rn.bf16x2.f32 %0, %1, %2;" : "=r"(lo) : "f"(l1), "f"(l0));
    return hi;
}

// ---------------------------------------------------------------------------
// Kernel A: bucket batch indices by element (y is exact one-hot).
// ---------------------------------------------------------------------------
__global__ void bucket_kernel(const float* __restrict__ y) {
    __shared__ int cnt[E_SZ];
    __shared__ int pfx[E_SZ + 1];
    int b = threadIdx.x;
    if (b < E_SZ) cnt[b] = 0;
    __syncthreads();
    int e = 0;
#pragma unroll
    for (int j = 1; j < E_SZ; j++)
        if (y[b * E_SZ + j] > 0.5f) e = j;
    int idx = atomicAdd(&cnt[e], 1);
    __syncthreads();
    if (b == 0) {
        int s = 0;
        for (int j = 0; j < E_SZ; j++) { pfx[j] = s; s += cnt[j]; }
        pfx[E_SZ] = s;
    }
    __syncthreads();
    g_order[pfx[e] + idx] = b;
    if (b <= E_SZ) g_bstart[b] = pfx[b];
}

// ---------------------------------------------------------------------------
// Kernel B1: AbigT[kp][m*160+k], (d,v) enumeration:
//   k<128: d=k>>4, v=k&15, i=(v+d)&15; d==0 diag U3[m,v,v] else U3[v,i]+U3[i,v]
//   128..135: v=k-128, i=v+8; 136..151: U2; 152: U1; rest 0.
// ---------------------------------------------------------------------------
__global__ void build_abig_kernel(const float* __restrict__ U3,
                                  const float* __restrict__ U2,
                                  const float* __restrict__ U1) {
    int o = blockIdx.x * 256 + threadIdx.x;
    if (o >= GSZ) return;
    int m = o / KTOT, k = o % KTOT;
    float vals[KW];
#pragma unroll
    for (int j = 0; j < KW; j++) vals[j] = 0.f;
    int v = -1, i = -1;
    if (k < 128) {
        int d = k >> 4;
        v = k & 15;
        i = (v + d) & 15;
        if (d == 0) i = -2;
    } else if (k < 136) {
        v = k - 128;
        i = v + 8;
    }
    if (v >= 0) {
        if (i == -2) {
            const float* p1 = U3 + ((size_t)(m * ELL + v) * ELL + v) * P3;
#pragma unroll
            for (int kp = 0; kp < P3; kp++) vals[kp] = p1[kp];
        } else {
            const float* p1 = U3 + ((size_t)(m * ELL + v) * ELL + i) * P3;
            const float* p2 = U3 + ((size_t)(m * ELL + i) * ELL + v) * P3;
#pragma unroll
            for (int kp = 0; kp < P3; kp++) vals[kp] = p1[kp] + p2[kp];
        }
    } else if (k >= 136 && k < 152) {
        int vv = k - 136;
#pragma unroll
        for (int k2 = 0; k2 < P2; k2++)
            vals[P3 + k2] = U2[(m * ELL + vv) * P2 + k2];
    } else if (k == 152) {
        vals[P3 + P2] = U1[m];
    }
#pragma unroll
    for (int j = 0; j < KW; j++)
        g_AbigT[j * GSZ + o] = vals[j];
}

// ---------------------------------------------------------------------------
// Kernel B2: G[ec, o] = sum_kp AbigT[kp, o] * W[ec, kp]; bf16 hi/lo split.
// ---------------------------------------------------------------------------
__global__ void __launch_bounds__(256) build_g_kernel(
    const float* __restrict__ wmax, const float* __restrict__ w2,
    const float* __restrict__ w1) {
    int o = blockIdx.x * 256 + threadIdx.x;
    int ec0 = blockIdx.y * 80;
    __shared__ __align__(8) float ws[KW][80];
    for (int idx = threadIdx.x; idx < KW * 80; idx += 256) {
        int kp = idx / 80, j = idx - kp * 80;
        int ec = ec0 + j, e = ec >> 7, c = ec & 127;
        float v;
        if (kp < P3) v = wmax[(e * P3 + kp) * C_SZ + c];
        else if (kp < P3 + P2) v = w2[(e * P2 + (kp - P3)) * C_SZ + c];
        else v = w1[e * C_SZ + c];
        ws[kp][j] = v;
    }
    __syncthreads();

    unsigned long long a2[KW];
#pragma unroll
    for (int kp = 0; kp < KW; kp++) {
        float a = g_AbigT[kp * GSZ + o];
        a2[kp] = pack2(a, a);
    }
    for (int j = 0; j < 80; j += 2) {
        unsigned long long acc2 = 0ull;
#pragma unroll
        for (int kp = 0; kp < KW; kp++)
            acc2 = fma2(a2[kp], *(const unsigned long long*)&ws[kp][j], acc2);
        float g0, g1;
        unpack2(g0, g1, acc2);
        size_t ecA = (size_t)(ec0 + j), ecB = ecA + 1;
        __nv_bfloat16 h0 = __float2bfloat16(g0);
        __nv_bfloat16 h1 = __float2bfloat16(g1);
        g_Ghi[ecA * GSZ + o] = h0;
        g_Glo[ecA * GSZ + o] = __float2bfloat16(g0 - __bfloat162float(h0));
        g_Ghi[ecB * GSZ + o] = h1;
        g_Glo[ecB * GSZ + o] = __float2bfloat16(g1 - __bfloat162float(h1));
    }
}

// ---------------------------------------------------------------------------
// Kernel Z: precompute z features per (b,c) row — full occupancy, no syncs.
// Warp handles one row rc = b*128+c. Lanes 0-15 hold x; shuffles gather the
// pair operands. Lane kk (+32,+64) computes pair kk, writes Zh/Zl (coalesced).
// ---------------------------------------------------------------------------
__global__ void __launch_bounds__(256) zbuild_kernel(const float* __restrict__ x) {
    int rc = blockIdx.x * 8 + (threadIdx.x >> 5);
    int lane = threadIdx.x & 31;
    float xv = (lane < ELL) ? x[(size_t)rc * ELL + lane] : 0.f;
    uint32_t* zh = g_Zh + (size_t)rc * KPAIR;
    uint32_t* zl = g_Zl + (size_t)rc * KPAIR;
#pragma unroll
    for (int it = 0; it < 3; it++) {
        int kk = lane + 32 * it;
        int v0, i0, v1, i1;
        if (kk < 64) {
            int d = kk >> 3;
            v0 = (kk & 7) * 2;
            i0 = (v0 + d) & 15;
            v1 = v0 + 1;
            i1 = (v0 + 1 + d) & 15;
        } else if (kk < 68) {
            v0 = (kk - 64) * 2;
            i0 = v0 + 8;
            v1 = v0 + 1;
            i1 = v0 + 9;
        } else if (kk < 76) {
            v0 = (kk - 68) * 2;
            i0 = 0;
            v1 = v0 + 1;
            i1 = 0;
        } else {
            v0 = i0 = v1 = i1 = 0;
        }
        // unconditional collectives (all 32 lanes)
        float xa0 = __shfl_sync(0xffffffffu, xv, v0);
        float xb0 = __shfl_sync(0xffffffffu, xv, i0);
        float xa1 = __shfl_sync(0xffffffffu, xv, v1);
        float xb1 = __shfl_sync(0xffffffffu, xv, i1);
        float z0 = (kk < 68) ? xa0 * xb0 : (kk < 76 ? xa0 : (kk == 76 ? 1.f : 0.f));
        float z1 = (kk < 68) ? xa1 * xb1 : (kk < 76 ? xa1 : 0.f);
        if (kk < KPAIR) {
            uint32_t lo;
            uint32_t hi = tsplit(z0, z1, lo);
            zh[kk] = hi;
            zl[kk] = lo;
        }
    }
}

// ---------------------------------------------------------------------------
// Kernel C: per (e,c) CTA, 192 threads (6 warps), NT=32 b-tile.
// A (bf16 hi/lo) staged to smem once; Z rows gathered from gmem per tile.
// Fragment feeds via ldmatrix.x4 (non-trans: Z[n][k] row-major IS the B frag).
// 6 independent MMA accumulator chains (hh/hl/lh x 2 n-frags).
// ---------------------------------------------------------------------------
#define LDSM4(D0, D1, D2, D3, ADDR)                                         \
    asm volatile("ldmatrix.sync.aligned.m8n8.x4.shared.b16 {%0,%1,%2,%3}, [%4];" \
                 : "=r"(D0), "=r"(D1), "=r"(D2), "=r"(D3) : "r"(ADDR))

#define MMA_BF16(CC, A0, A1, A2, A3, B0, B1)                                \
    asm volatile(                                                           \
        "mma.sync.aligned.m16n8k16.row.col.f32.bf16.bf16.f32 "              \
        "{%0,%1,%2,%3}, {%4,%5,%6,%7}, {%8,%9}, {%0,%1,%2,%3};"             \
        : "+f"(CC[0]), "+f"(CC[1]), "+f"(CC[2]), "+f"(CC[3])                \
        : "r"(A0), "r"(A1), "r"(A2), "r"(A3), "r"(B0), "r"(B1))

__global__ void __launch_bounds__(192, 4) contract_kernel(
    const float* __restrict__ x, float* __restrict__ out) {
    int c = blockIdx.x, e = blockIdx.y;
    int ec = e * C_SZ + c;
    int t = threadIdx.x;
    int warp = t >> 5, lane = t & 31;
    int mi = warp >> 1, ni = warp & 1;
    int r = lane >> 2, q = lane & 3;

    __shared__ __align__(16) uint32_t Ah[MROWS * LDA], Al[MROWS * LDA];
    __shared__ __align__(16) uint32_t Zh_s[NT * LDA], Zl_s[NT * LDA];
    __shared__ float xs[NT * XSW];
    __shared__ int border[NT];

    // Stage A (hi+lo) into smem once. Rows are 20 uint4 in gmem.
    {
        const uint4* gh = (const uint4*)g_Ghi + (size_t)ec * (MROWS * 20);
        const uint4* gl = (const uint4*)g_Glo + (size_t)ec * (MROWS * 20);
        for (int p = t; p < MROWS * 20; p += 192) {
            int m = p / 20, j = p - m * 20;
            *(uint4*)&Ah[m * LDA + j * 4] = gh[p];
            *(uint4*)&Al[m * LDA + j * 4] = gl[p];
        }
    }

    // LDSM lane addresses (byte offsets into shared space)
    uint32_t saAh = (uint32_t)__cvta_generic_to_shared(Ah);
    uint32_t saAl = (uint32_t)__cvta_generic_to_shared(Al);
    uint32_t saZh = (uint32_t)__cvta_generic_to_shared(Zh_s);
    uint32_t saZl = (uint32_t)__cvta_generic_to_shared(Zl_s);
    int rowA = mi * 16 + (lane & 7) + ((lane >> 3) & 1) * 8;
    int colA = (lane >> 4) * 4;
    uint32_t aAh = saAh + (uint32_t)(rowA * LDA + colA) * 4u;
    uint32_t aAl = saAl + (uint32_t)(rowA * LDA + colA) * 4u;
    int rowB = ni * 8 + (lane & 7);
    int colB = (lane >> 3) * 4;
    uint32_t aB0h = saZh + (uint32_t)(rowB * LDA + colB) * 4u;
    uint32_t aB0l = saZl + (uint32_t)(rowB * LDA + colB) * 4u;
    uint32_t aB1h = aB0h + 16u * LDA * 4u;
    uint32_t aB1l = aB0l + 16u * LDA * 4u;

    int b0 = g_bstart[e], b1 = g_bstart[e + 1];
    for (int tb = b0; tb < b1; tb += NT) {
        int nb = min(NT, b1 - tb);

        // phase 1: x + border load, Z row gather
        for (int idx = t; idx < NT * ELL; idx += 192) {
            int slot = idx >> 4, ii = idx & 15;
            float vv = 0.f;
            if (slot < nb) {
                int bidx = g_order[tb + slot];
                if (ii == 0) border[slot] = bidx;
                vv = x[((size_t)bidx * C_SZ + c) * ELL + ii];
            }
            xs[slot * XSW + ii] = vv;
        }
        for (int n = warp; n < nb; n += 6) {
            size_t row = (size_t)g_order[tb + n] * C_SZ + c;
            if (lane < 20) {
                uint4 vh = ((const uint4*)g_Zh)[row * 20 + lane];
                *(uint4*)&Zh_s[n * LDA + lane * 4] = vh;
                uint4 vl = ((const uint4*)g_Zl)[row * 20 + lane];
                *(uint4*)&Zl_s[n * LDA + lane * 4] = vl;
            }
        }
        __syncthreads();

        // phase 2: GEMM, 6 independent chains
        float acc[6][4];
#pragma unroll
        for (int s = 0; s < 6; s++)
#pragma unroll
            for (int j = 0; j < 4; j++) acc[s][j] = 0.f;

#pragma unroll
        for (int g2 = 0; g2 < 5; g2++) {
            uint32_t off2 = (uint32_t)g2 * 64u;
            uint32_t ah0, ah1, ah2, ah3, ap0, ap1, ap2, ap3;
            uint32_t al0, al1, al2, al3, aq0, aq1, aq2, aq3;
            uint32_t bh0, bh1, bh2, bh3, bl0, bl1, bl2, bl3;
            uint32_t ch0, ch1, ch2, ch3, cl0, cl1, cl2, cl3;
            LDSM4(ah0, ah1, ah2, ah3, aAh + off2);        // A hi, kstep 2g2
            LDSM4(ap0, ap1, ap2, ap3, aAh + off2 + 32u);  // A hi, kstep 2g2+1
            LDSM4(al0, al1, al2, al3, aAl + off2);        // A lo, kstep 2g2
            LDSM4(aq0, aq1, aq2, aq3, aAl + off2 + 32u);  // A lo, kstep 2g2+1
            LDSM4(bh0, bh1, bh2, bh3, aB0h + off2);       // B hi frag0, both
            LDSM4(bl0, bl1, bl2, bl3, aB0l + off2);       // B lo frag0
            LDSM4(ch0, ch1, ch2, ch3, aB1h + off2);       // B hi frag1
            LDSM4(cl0, cl1, cl2, cl3, aB1l + off2);       // B lo frag1
            // kstep 2g2
            MMA_BF16(acc[0], ah0, ah1, ah2, ah3, bh0, bh1);
            MMA_BF16(acc[1], ah0, ah1, ah2, ah3, bl0, bl1);
            MMA_BF16(acc[2], al0, al1, al2, al3, bh0, bh1);
            MMA_BF16(acc[3], ah0, ah1, ah2, ah3, ch0, ch1);
            MMA_BF16(acc[4], ah0, ah1, ah2, ah3, cl0, cl1);
            MMA_BF16(acc[5], al0, al1, al2, al3, ch0, ch1);
            // kstep 2g2+1
            MMA_BF16(acc[0], ap0, ap1, ap2, ap3, bh2, bh3);
            MMA_BF16(acc[1], ap0, ap1, ap2, ap3, bl2, bl3);
            MMA_BF16(acc[2], aq0, aq1, aq2, aq3, bh2, bh3);
            MMA_BF16(acc[3], ap0, ap1, ap2, ap3, ch2, ch3);
            MMA_BF16(acc[4], ap0, ap1, ap2, ap3, cl2, cl3);
            MMA_BF16(acc[5], aq0, aq1, aq2, aq3, ch2, ch3);
        }

        // epilogue: out[w,b] = sum_xx xs[b][xx] * Q[xx,b]
#pragma unroll
        for (int f = 0; f < 2; f++) {
            float c0 = acc[3 * f][0] + acc[3 * f + 1][0] + acc[3 * f + 2][0];
            float c1 = acc[3 * f][1] + acc[3 * f + 1][1] + acc[3 * f + 2][1];
            float c2 = acc[3 * f][2] + acc[3 * f + 1][2] + acc[3 * f + 2][2];
            float c3 = acc[3 * f][3] + acc[3 * f + 1][3] + acc[3 * f + 2][3];
            int bc0 = f * 16 + ni * 8 + 2 * q;
            int bc1 = bc0 + 1;
            float p0 = c0 * xs[bc0 * XSW + r] + c2 * xs[bc0 * XSW + r + 8];
            float p1 = c1 * xs[bc1 * XSW + r] + c3 * xs[bc1 * XSW + r + 8];
#pragma unroll
            for (int off = 4; off <= 16; off <<= 1) {
                p0 += __shfl_xor_sync(0xffffffffu, p0, off);
                p1 += __shfl_xor_sync(0xffffffffu, p1, off);
            }
            if (lane < 4) {
                if (bc0 < nb) out[(size_t)border[bc0] * OUT_STRIDE + c * EQ + mi] = p0;
                if (bc1 < nb) out[(size_t)border[bc1] * OUT_STRIDE + c * EQ + mi] = p1;
            }
        }
        __syncthreads();
    }
}

// ---------------------------------------------------------------------------
extern "C" void kernel_launch(void* const* d_in, const int* in_sizes, int n_in,
                              void* d_out, int out_size) {
    const float* x    = (const float*)d_in[0];
    const float* y    = (const float*)d_in[1];
    const float* U3   = (const float*)d_in[2];
    const float* U2   = (const float*)d_in[3];
    const float* U1   = (const float*)d_in[4];
    const float* wmax = (const float*)d_in[5];
    const float* w2   = (const float*)d_in[6];
    const float* w1   = (const float*)d_in[7];
    float* out = (float*)d_out;

    bucket_kernel<<<1, B_SZ>>>(y);
    build_abig_kernel<<<30, 256>>>(U3, U2, U1);
    build_g_kernel<<<dim3(30, 16), 256>>>(wmax, w2, w1);
    zbuild_kernel<<<NROW / 8, 256>>>(x);
    contract_kernel<<<dim3(C_SZ, E_SZ), 192>>>(x, out);
}

// round 14
// speedup vs baseline: 1.1469x; 1.1469x over previous
#include <cuda_runtime.h>
#include <cuda_bf16.h>
#include <cstdint>

#define B_SZ 1024
#define C_SZ 128
#define ELL 16
#define EQ 3
#define E_SZ 10
#define P3 23
#define P2 5
#define OUT_STRIDE 384
#define MROWS 48           // (w,xx) rows, m = w*16 + xx
#define KTOT 160
#define KPAIR 80
#define KW 29              // 23 + 5 + 1 weight slots
#define NT 32              // b-tile
#define GSZ (MROWS * KTOT) // 7680
#define LDA 84             // smem pair-stride (21 x 16B, LDSM conflict-free)
#define ZROW 160           // g_Z u32 per row (interleaved hi/lo, 40 chunks)
#define NROW (B_SZ * C_SZ)

__device__ int g_order[B_SZ];
__device__ int g_bstart[E_SZ + 1];
__device__ __align__(16) float g_AbigT[KW * GSZ];
__device__ __align__(16) __nv_bfloat16 g_Ghi[E_SZ * C_SZ * GSZ];
__device__ __align__(16) __nv_bfloat16 g_Glo[E_SZ * C_SZ * GSZ];
__device__ __align__(16) uint32_t g_Z[(size_t)NROW * ZROW];  // 84 MB interleaved

// ---- packed f32x2 helpers ----
static __device__ __forceinline__ unsigned long long pack2(float lo, float hi) {
    unsigned long long r;
    asm("mov.b64 %0, {%1, %2};" : "=l"(r) : "f"(lo), "f"(hi));
    return r;
}
static __device__ __forceinline__ void unpack2(float& lo, float& hi, unsigned long long v) {
    asm("mov.b64 {%0, %1}, %2;" : "=f"(lo), "=f"(hi) : "l"(v));
}
static __device__ __forceinline__ unsigned long long fma2(unsigned long long a,
                                                          unsigned long long b,
                                                          unsigned long long c) {
    unsigned long long d;
    asm("fma.rn.f32x2 %0, %1, %2, %3;" : "=l"(d) : "l"(a), "l"(b), "l"(c));
    return d;
}

// truncation split: hi = top-16-bits (exact), lo = RN-bf16 of remainder
static __device__ __forceinline__ uint32_t tsplit(float z0, float z1, uint32_t& lo) {
    uint32_t u0 = __float_as_uint(z0), u1 = __float_as_uint(z1);
    float l0 = z0 - __uint_as_float(u0 & 0xFFFF0000u);
    float l1 = z1 - __uint_as_float(u1 & 0xFFFF0000u);
    uint32_t hi;
    asm("prmt.b32 %0, %1, %2, 0x7632;" : "=r"(hi) : "r"(u0), "r"(u1));
    asm("cvt.rn.bf16x2.f32 %0, %1, %2;" : "=r"(lo) : "f"(l1), "f"(l0));
    return hi;
}

#define CP_ASYNC16(dst, src) \
    asm volatile("cp.async.cg.shared.global [%0], [%1], 16;" :: "r"(dst), "l"(src))
#define CP_COMMIT() asm volatile("cp.async.commit_group;")
#define CP_WAIT0() asm volatile("cp.async.wait_group 0;")
#define CP_WAIT1() asm volatile("cp.async.wait_group 1;")

// ---------------------------------------------------------------------------
// Kernel A: bucket batch indices by element (y is exact one-hot).
// ---------------------------------------------------------------------------
__global__ void bucket_kernel(const float* __restrict__ y) {
    __shared__ int cnt[E_SZ];
    __shared__ int pfx[E_SZ + 1];
    int b = threadIdx.x;
    if (b < E_SZ) cnt[b] = 0;
    __syncthreads();
    int e = 0;
#pragma unroll
    for (int j = 1; j < E_SZ; j++)
        if (y[b * E_SZ + j] > 0.5f) e = j;
    int idx = atomicAdd(&cnt[e], 1);
    __syncthreads();
    if (b == 0) {
        int s = 0;
        for (int j = 0; j < E_SZ; j++) { pfx[j] = s; s += cnt[j]; }
        pfx[E_SZ] = s;
    }
    __syncthreads();
    g_order[pfx[e] + idx] = b;
    if (b <= E_SZ) g_bstart[b] = pfx[b];
}

// ---------------------------------------------------------------------------
// Kernel B1: AbigT[kp][m*160+k], (d,v) enumeration.
// ---------------------------------------------------------------------------
__global__ void build_abig_kernel(const float* __restrict__ U3,
                                  const float* __restrict__ U2,
                                  const float* __restrict__ U1) {
    int o = blockIdx.x * 256 + threadIdx.x;
    if (o >= GSZ) return;
    int m = o / KTOT, k = o % KTOT;
    float vals[KW];
#pragma unroll
    for (int j = 0; j < KW; j++) vals[j] = 0.f;
    int v = -1, i = -1;
    if (k < 128) {
        int d = k >> 4;
        v = k & 15;
        i = (v + d) & 15;
        if (d == 0) i = -2;
    } else if (k < 136) {
        v = k - 128;
        i = v + 8;
    }
    if (v >= 0) {
        if (i == -2) {
            const float* p1 = U3 + ((size_t)(m * ELL + v) * ELL + v) * P3;
#pragma unroll
            for (int kp = 0; kp < P3; kp++) vals[kp] = p1[kp];
        } else {
            const float* p1 = U3 + ((size_t)(m * ELL + v) * ELL + i) * P3;
            const float* p2 = U3 + ((size_t)(m * ELL + i) * ELL + v) * P3;
#pragma unroll
            for (int kp = 0; kp < P3; kp++) vals[kp] = p1[kp] + p2[kp];
        }
    } else if (k >= 136 && k < 152) {
        int vv = k - 136;
#pragma unroll
        for (int k2 = 0; k2 < P2; k2++)
            vals[P3 + k2] = U2[(m * ELL + vv) * P2 + k2];
    } else if (k == 152) {
        vals[P3 + P2] = U1[m];
    }
#pragma unroll
    for (int j = 0; j < KW; j++)
        g_AbigT[j * GSZ + o] = vals[j];
}

// ---------------------------------------------------------------------------
// Kernel B2: G[ec, o] = sum_kp AbigT[kp, o] * W[ec, kp]; bf16 hi/lo split.
// ---------------------------------------------------------------------------
__global__ void __launch_bounds__(256) build_g_kernel(
    const float* __restrict__ wmax, const float* __restrict__ w2,
    const float* __restrict__ w1) {
    int o = blockIdx.x * 256 + threadIdx.x;
    int ec0 = blockIdx.y * 80;
    __shared__ __align__(8) float ws[KW][80];
    for (int idx = threadIdx.x; idx < KW * 80; idx += 256) {
        int kp = idx / 80, j = idx - kp * 80;
        int ec = ec0 + j, e = ec >> 7, c = ec & 127;
        float v;
        if (kp < P3) v = wmax[(e * P3 + kp) * C_SZ + c];
        else if (kp < P3 + P2) v = w2[(e * P2 + (kp - P3)) * C_SZ + c];
        else v = w1[e * C_SZ + c];
        ws[kp][j] = v;
    }
    __syncthreads();

    unsigned long long a2[KW];
#pragma unroll
    for (int kp = 0; kp < KW; kp++) {
        float a = g_AbigT[kp * GSZ + o];
        a2[kp] = pack2(a, a);
    }
    for (int j = 0; j < 80; j += 2) {
        unsigned long long acc2 = 0ull;
#pragma unroll
        for (int kp = 0; kp < KW; kp++)
            acc2 = fma2(a2[kp], *(const unsigned long long*)&ws[kp][j], acc2);
        float g0, g1;
        unpack2(g0, g1, acc2);
        size_t ecA = (size_t)(ec0 + j), ecB = ecA + 1;
        __nv_bfloat16 h0 = __float2bfloat16(g0);
        __nv_bfloat16 h1 = __float2bfloat16(g1);
        g_Ghi[ecA * GSZ + o] = h0;
        g_Glo[ecA * GSZ + o] = __float2bfloat16(g0 - __bfloat162float(h0));
        g_Ghi[ecB * GSZ + o] = h1;
        g_Glo[ecB * GSZ + o] = __float2bfloat16(g1 - __bfloat162float(h1));
    }
}

// ---------------------------------------------------------------------------
// Kernel Z: precompute z per (b,c) row. Interleaved layout: group g (4 pairs)
// occupies u32 [g*8 .. g*8+3] = hi, [g*8+4 .. g*8+7] = lo  (chunk 2g / 2g+1).
// ---------------------------------------------------------------------------
__global__ void __launch_bounds__(256) zbuild_kernel(const float* __restrict__ x) {
    int rc = blockIdx.x * 8 + (threadIdx.x >> 5);
    int lane = threadIdx.x & 31;
    float xv = (lane < ELL) ? x[(size_t)rc * ELL + lane] : 0.f;
    uint32_t* zrow = g_Z + (size_t)rc * ZROW;
#pragma unroll
    for (int it = 0; it < 3; it++) {
        int kk = lane + 32 * it;
        int v0, i0, v1, i1;
        if (kk < 64) {
            int d = kk >> 3;
            v0 = (kk & 7) * 2;
            i0 = (v0 + d) & 15;
            v1 = v0 + 1;
            i1 = (v0 + 1 + d) & 15;
        } else if (kk < 68) {
            v0 = (kk - 64) * 2;
            i0 = v0 + 8;
            v1 = v0 + 1;
            i1 = v0 + 9;
        } else if (kk < 76) {
            v0 = (kk - 68) * 2;
            i0 = 0;
            v1 = v0 + 1;
            i1 = 0;
        } else {
            v0 = i0 = v1 = i1 = 0;
        }
        float xa0 = __shfl_sync(0xffffffffu, xv, v0);
        float xb0 = __shfl_sync(0xffffffffu, xv, i0);
        float xa1 = __shfl_sync(0xffffffffu, xv, v1);
        float xb1 = __shfl_sync(0xffffffffu, xv, i1);
        float z0 = (kk < 68) ? xa0 * xb0 : (kk < 76 ? xa0 : (kk == 76 ? 1.f : 0.f));
        float z1 = (kk < 68) ? xa1 * xb1 : (kk < 76 ? xa1 : 0.f);
        if (kk < KPAIR) {
            uint32_t lo;
            uint32_t hi = tsplit(z0, z1, lo);
            int g = kk >> 2, w = kk & 3;
            zrow[g * 8 + w] = hi;
            zrow[g * 8 + 4 + w] = lo;
        }
    }
}

// ---------------------------------------------------------------------------
// Kernel C: per (e,c) CTA, 192 threads, NT=32, double-buffered cp.async Z
// gather overlapped with GEMM. x reconstructed from Z linear block (hi+lo).
// ---------------------------------------------------------------------------
#define LDSM4(D0, D1, D2, D3, ADDR)                                         \
    asm volatile("ldmatrix.sync.aligned.m8n8.x4.shared.b16 {%0,%1,%2,%3}, [%4];" \
                 : "=r"(D0), "=r"(D1), "=r"(D2), "=r"(D3) : "r"(ADDR))

#define MMA_BF16(CC, A0, A1, A2, A3, B0, B1)                                \
    asm volatile(                                                           \
        "mma.sync.aligned.m16n8k16.row.col.f32.bf16.bf16.f32 "              \
        "{%0,%1,%2,%3}, {%4,%5,%6,%7}, {%8,%9}, {%0,%1,%2,%3};"             \
        : "+f"(CC[0]), "+f"(CC[1]), "+f"(CC[2]), "+f"(CC[3])                \
        : "r"(A0), "r"(A1), "r"(A2), "r"(A3), "r"(B0), "r"(B1))

__global__ void __launch_bounds__(192, 2) contract_kernel(float* __restrict__ out) {
    int c = blockIdx.x, e = blockIdx.y;
    int ec = e * C_SZ + c;
    int t = threadIdx.x;
    int warp = t >> 5, lane = t & 31;
    int mi = warp >> 1, ni = warp & 1;
    int q = lane & 3, r = lane >> 2;

    int b0 = g_bstart[e], b1 = g_bstart[e + 1];
    if (b1 <= b0) return;
    int ntiles = (b1 - b0 + NT - 1) / NT;

    __shared__ __align__(16) uint32_t Ah[MROWS * LDA], Al[MROWS * LDA];
    __shared__ __align__(16) uint32_t Zh_s[2 * NT * LDA], Zl_s[2 * NT * LDA];
    __shared__ int border[2][NT];

    // Stage A (hi+lo) into smem once. Rows are 20 uint4 in gmem.
    {
        const uint4* gh = (const uint4*)g_Ghi + (size_t)ec * (MROWS * 20);
        const uint4* gl = (const uint4*)g_Glo + (size_t)ec * (MROWS * 20);
        for (int p = t; p < MROWS * 20; p += 192) {
            int m = p / 20, j = p - m * 20;
            *(uint4*)&Ah[m * LDA + j * 4] = gh[p];
            *(uint4*)&Al[m * LDA + j * 4] = gl[p];
        }
    }

    uint32_t saAh = (uint32_t)__cvta_generic_to_shared(Ah);
    uint32_t saAl = (uint32_t)__cvta_generic_to_shared(Al);
    uint32_t saZh = (uint32_t)__cvta_generic_to_shared(Zh_s);
    uint32_t saZl = (uint32_t)__cvta_generic_to_shared(Zl_s);

    // gather one tile's Z rows into buffer `buf` via cp.async
    auto gather = [&](int ti, int buf) {
        int tb = b0 + ti * NT;
        int nbt = min(NT, b1 - tb);
        uint32_t bufoff = (uint32_t)buf * NT * LDA * 4u;
        for (int n = warp; n < nbt; n += 6) {
            int bidx = g_order[tb + n];
            if (lane == 0) border[buf][n] = bidx;
            const uint32_t* src = g_Z + ((size_t)bidx * C_SZ + c) * ZROW;
            // chunk j = lane (0..31) and 32+lane (lane<8)
            {
                int j = lane;
                uint32_t dst = ((j & 1) ? saZl : saZh) + bufoff +
                               ((uint32_t)n * LDA + (uint32_t)(j >> 1) * 4u) * 4u;
                CP_ASYNC16(dst, (const char*)(src + j * 4));
            }
            if (lane < 8) {
                int j = 32 + lane;
                uint32_t dst = ((j & 1) ? saZl : saZh) + bufoff +
                               ((uint32_t)n * LDA + (uint32_t)(j >> 1) * 4u) * 4u;
                CP_ASYNC16(dst, (const char*)(src + j * 4));
            }
        }
    };

    // LDSM lane addresses
    int rowA = mi * 16 + (lane & 7) + ((lane >> 3) & 1) * 8;
    int colA = (lane >> 4) * 4;
    uint32_t aAh = saAh + (uint32_t)(rowA * LDA + colA) * 4u;
    uint32_t aAl = saAl + (uint32_t)(rowA * LDA + colA) * 4u;
    int rowB = ni * 8 + (lane & 7);
    int colB = (lane >> 3) * 4;
    uint32_t bOff = (uint32_t)(rowB * LDA + colB) * 4u;

    gather(0, 0);
    CP_COMMIT();

    for (int ti = 0; ti < ntiles; ti++) {
        int cur = ti & 1;
        if (ti + 1 < ntiles) {
            gather(ti + 1, 1 - cur);
            CP_COMMIT();
            CP_WAIT1();
        } else {
            CP_WAIT0();
        }
        __syncthreads();

        uint32_t bufoff = (uint32_t)cur * NT * LDA * 4u;
        uint32_t aB0h = saZh + bufoff + bOff;
        uint32_t aB0l = saZl + bufoff + bOff;
        uint32_t aB1h = aB0h + 16u * LDA * 4u;
        uint32_t aB1l = aB0l + 16u * LDA * 4u;

        float acc[6][4];
#pragma unroll
        for (int s = 0; s < 6; s++)
#pragma unroll
            for (int j = 0; j < 4; j++) acc[s][j] = 0.f;

#pragma unroll
        for (int g2 = 0; g2 < 5; g2++) {
            uint32_t off2 = (uint32_t)g2 * 64u;
            uint32_t ah0, ah1, ah2, ah3, ap0, ap1, ap2, ap3;
            uint32_t al0, al1, al2, al3, aq0, aq1, aq2, aq3;
            uint32_t bh0, bh1, bh2, bh3, bl0, bl1, bl2, bl3;
            uint32_t ch0, ch1, ch2, ch3, cl0, cl1, cl2, cl3;
            LDSM4(ah0, ah1, ah2, ah3, aAh + off2);
            LDSM4(ap0, ap1, ap2, ap3, aAh + off2 + 32u);
            LDSM4(al0, al1, al2, al3, aAl + off2);
            LDSM4(aq0, aq1, aq2, aq3, aAl + off2 + 32u);
            LDSM4(bh0, bh1, bh2, bh3, aB0h + off2);
            LDSM4(bl0, bl1, bl2, bl3, aB0l + off2);
            LDSM4(ch0, ch1, ch2, ch3, aB1h + off2);
            LDSM4(cl0, cl1, cl2, cl3, aB1l + off2);
            MMA_BF16(acc[0], ah0, ah1, ah2, ah3, bh0, bh1);
            MMA_BF16(acc[1], ah0, ah1, ah2, ah3, bl0, bl1);
            MMA_BF16(acc[2], al0, al1, al2, al3, bh0, bh1);
            MMA_BF16(acc[3], ah0, ah1, ah2, ah3, ch0, ch1);
            MMA_BF16(acc[4], ah0, ah1, ah2, ah3, cl0, cl1);
            MMA_BF16(acc[5], al0, al1, al2, al3, ch0, ch1);
            MMA_BF16(acc[0], ap0, ap1, ap2, ap3, bh2, bh3);
            MMA_BF16(acc[1], ap0, ap1, ap2, ap3, bl2, bl3);
            MMA_BF16(acc[2], aq0, aq1, aq2, aq3, bh2, bh3);
            MMA_BF16(acc[3], ap0, ap1, ap2, ap3, ch2, ch3);
            MMA_BF16(acc[4], ap0, ap1, ap2, ap3, cl2, cl3);
            MMA_BF16(acc[5], aq0, aq1, aq2, aq3, ch2, ch3);
        }

        // x reconstruction from Z linear block: pair p = 68 + (idx>>1)
        auto xval = [&](int n, int idx) -> float {
            int p = 68 + (idx >> 1);
            uint32_t h = Zh_s[cur * NT * LDA + n * LDA + p];
            uint32_t l = Zl_s[cur * NT * LDA + n * LDA + p];
            uint32_t hs = (idx & 1) ? (h & 0xFFFF0000u) : (h << 16);
            uint32_t ls = (idx & 1) ? (l & 0xFFFF0000u) : (l << 16);
            return __uint_as_float(hs) + __uint_as_float(ls);
        };

        int tb = b0 + ti * NT;
        int nb = min(NT, b1 - tb);
#pragma unroll
        for (int f = 0; f < 2; f++) {
            float c0 = acc[3 * f][0] + acc[3 * f + 1][0] + acc[3 * f + 2][0];
            float c1 = acc[3 * f][1] + acc[3 * f + 1][1] + acc[3 * f + 2][1];
            float c2 = acc[3 * f][2] + acc[3 * f + 1][2] + acc[3 * f + 2][2];
            float c3 = acc[3 * f][3] + acc[3 * f + 1][3] + acc[3 * f + 2][3];
            int bc0 = f * 16 + ni * 8 + 2 * q;
            int bc1 = bc0 + 1;
            float p0 = c0 * xval(bc0, r) + c2 * xval(bc0, r + 8);
            float p1 = c1 * xval(bc1, r) + c3 * xval(bc1, r + 8);
#pragma unroll
            for (int off = 4; off <= 16; off <<= 1) {
                p0 += __shfl_xor_sync(0xffffffffu, p0, off);
                p1 += __shfl_xor_sync(0xffffffffu, p1, off);
            }
            if (lane < 4) {
                if (bc0 < nb) out[(size_t)border[cur][bc0] * OUT_STRIDE + c * EQ + mi] = p0;
                if (bc1 < nb) out[(size_t)border[cur][bc1] * OUT_STRIDE + c * EQ + mi] = p1;
            }
        }
        __syncthreads();
    }
}

// ---------------------------------------------------------------------------
extern "C" void kernel_launch(void* const* d_in, const int* in_sizes, int n_in,
                              void* d_out, int out_size) {
    const float* x    = (const float*)d_in[0];
    const float* y    = (const float*)d_in[1];
    const float* U3   = (const float*)d_in[2];
    const float* U2   = (const float*)d_in[3];
    const float* U1   = (const float*)d_in[4];
    const float* wmax = (const float*)d_in[5];
    const float* w2   = (const float*)d_in[6];
    const float* w1   = (const float*)d_in[7];
    float* out = (float*)d_out;

    bucket_kernel<<<1, B_SZ>>>(y);
    build_abig_kernel<<<30, 256>>>(U3, U2, U1);
    build_g_kernel<<<dim3(30, 16), 256>>>(wmax, w2, w1);
    zbuild_kernel<<<NROW / 8, 256>>>(x);
    contract_kernel<<<dim3(C_SZ, E_SZ), 192>>>(out);
}

// round 16
// speedup vs baseline: 1.4094x; 1.2288x over previous
#include <cuda_runtime.h>
#include <cuda_bf16.h>
#include <cstdint>

#define B_SZ 1024
#define C_SZ 128
#define ELL 16
#define EQ 3
#define E_SZ 10
#define P3 23
#define P2 5
#define OUT_STRIDE 384
#define MROWS 48           // (w,xx) rows, m = w*16 + xx
#define KTOT 160
#define KPAIR 80
#define KW 29              // 23 + 5 + 1 weight slots
#define NT 32              // b-tile
#define GSZ (MROWS * KTOT) // 7680
#define LDA 84             // smem pair-stride (21 x 16B, LDSM conflict-free)
#define ZROW 160           // g_Z u32 per row (interleaved hi/lo, 40 chunks)
#define NROW (B_SZ * C_SZ)
#define ZB_CTAS (NROW / 8)   // 16384
#define BG_CTAS 480          // buildG: 30 o-tiles x 16 ec-tiles

__device__ int g_order[B_SZ];
__device__ int g_bstart[E_SZ + 1];
__device__ __align__(16) __nv_bfloat16 g_Ghi[E_SZ * C_SZ * GSZ];
__device__ __align__(16) __nv_bfloat16 g_Glo[E_SZ * C_SZ * GSZ];
__device__ __align__(16) uint32_t g_Z[(size_t)NROW * ZROW];  // 84 MB interleaved

// ---- packed f32x2 helpers ----
static __device__ __forceinline__ unsigned long long pack2(float lo, float hi) {
    unsigned long long r;
    asm("mov.b64 %0, {%1, %2};" : "=l"(r) : "f"(lo), "f"(hi));
    return r;
}
static __device__ __forceinline__ void unpack2(float& lo, float& hi, unsigned long long v) {
    asm("mov.b64 {%0, %1}, %2;" : "=f"(lo), "=f"(hi) : "l"(v));
}
static __device__ __forceinline__ unsigned long long fma2(unsigned long long a,
                                                          unsigned long long b,
                                                          unsigned long long c) {
    unsigned long long d;
    asm("fma.rn.f32x2 %0, %1, %2, %3;" : "=l"(d) : "l"(a), "l"(b), "l"(c));
    return d;
}

// truncation split: hi = top-16-bits (exact), lo = RN-bf16 of remainder
static __device__ __forceinline__ uint32_t tsplit(float z0, float z1, uint32_t& lo) {
    uint32_t u0 = __float_as_uint(z0), u1 = __float_as_uint(z1);
    float l0 = z0 - __uint_as_float(u0 & 0xFFFF0000u);
    float l1 = z1 - __uint_as_float(u1 & 0xFFFF0000u);
    uint32_t hi;
    asm("prmt.b32 %0, %1, %2, 0x7632;" : "=r"(hi) : "r"(u0), "r"(u1));
    asm("cvt.rn.bf16x2.f32 %0, %1, %2;" : "=r"(lo) : "f"(l1), "f"(l0));
    return hi;
}

#define CP_ASYNC16(dst, src) \
    asm volatile("cp.async.cg.shared.global [%0], [%1], 16;" :: "r"(dst), "l"(src))
#define CP_COMMIT() asm volatile("cp.async.commit_group;")
#define CP_WAIT0() asm volatile("cp.async.wait_group 0;")
#define CP_WAIT1() asm volatile("cp.async.wait_group 1;")

// ---------------------------------------------------------------------------
// MEGA prologue kernel: one launch, three independent jobs by blockIdx.
//   bx == 0                : bucket (y one-hot -> g_order/g_bstart)
//   1 <= bx <= BG_CTAS     : buildG (Abig computed inline from U3/U2/U1)
//   bx > BG_CTAS           : zbuild (z features per (b,c) row)
// ---------------------------------------------------------------------------
__global__ void __launch_bounds__(256) mega_kernel(
    const float* __restrict__ x, const float* __restrict__ y,
    const float* __restrict__ U3, const float* __restrict__ U2,
    const float* __restrict__ U1, const float* __restrict__ wmax,
    const float* __restrict__ w2, const float* __restrict__ w1) {
    int bx = blockIdx.x;
    int tid = threadIdx.x;

    if (bx == 0) {
        // ---- bucket: 256 threads, 4 b's each ----
        __shared__ int cnt[E_SZ];
        __shared__ int pfx[E_SZ + 1];
        if (tid < E_SZ) cnt[tid] = 0;
        __syncthreads();
        int mye[4], myidx[4];
#pragma unroll
        for (int j = 0; j < 4; j++) {
            int b = tid * 4 + j;
            int e = 0;
#pragma unroll
            for (int k = 1; k < E_SZ; k++)
                if (y[b * E_SZ + k] > 0.5f) e = k;
            mye[j] = e;
            myidx[j] = atomicAdd(&cnt[e], 1);
        }
        __syncthreads();
        if (tid == 0) {
            int s = 0;
            for (int j = 0; j < E_SZ; j++) { pfx[j] = s; s += cnt[j]; }
            pfx[E_SZ] = s;
        }
        __syncthreads();
#pragma unroll
        for (int j = 0; j < 4; j++)
            g_order[pfx[mye[j]] + myidx[j]] = tid * 4 + j;
        if (tid <= E_SZ) g_bstart[tid] = pfx[tid];
        return;
    }

    if (bx <= BG_CTAS) {
        // ---- buildG with inline Abig ----
        int idx = bx - 1;
        int obx = idx % 30, eby = idx / 30;  // obx<30, eby<16
        int o = obx * 256 + tid;             // 0..7679
        int ec0 = eby * 80;
        __shared__ __align__(8) float ws[KW][80];
        for (int ii = tid; ii < KW * 80; ii += 256) {
            int kp = ii / 80, j = ii - kp * 80;
            int ec = ec0 + j, e = ec >> 7, c = ec & 127;
            float v;
            if (kp < P3) v = wmax[(e * P3 + kp) * C_SZ + c];
            else if (kp < P3 + P2) v = w2[(e * P2 + (kp - P3)) * C_SZ + c];
            else v = w1[e * C_SZ + c];
            ws[kp][j] = v;
        }
        __syncthreads();

        // inline Abig row o
        float vals[KW];
#pragma unroll
        for (int j = 0; j < KW; j++) vals[j] = 0.f;
        {
            int m = o / KTOT, k = o % KTOT;
            int v = -1, i = -1;
            if (k < 128) {
                int d = k >> 4;
                v = k & 15;
                i = (v + d) & 15;
                if (d == 0) i = -2;
            } else if (k < 136) {
                v = k - 128;
                i = v + 8;
            }
            if (v >= 0) {
                if (i == -2) {
                    const float* p1 = U3 + ((size_t)(m * ELL + v) * ELL + v) * P3;
#pragma unroll
                    for (int kp = 0; kp < P3; kp++) vals[kp] = p1[kp];
                } else {
                    const float* p1 = U3 + ((size_t)(m * ELL + v) * ELL + i) * P3;
                    const float* p2 = U3 + ((size_t)(m * ELL + i) * ELL + v) * P3;
#pragma unroll
                    for (int kp = 0; kp < P3; kp++) vals[kp] = p1[kp] + p2[kp];
                }
            } else if (k >= 136 && k < 152) {
                int vv = k - 136;
#pragma unroll
                for (int k2 = 0; k2 < P2; k2++)
                    vals[P3 + k2] = U2[(m * ELL + vv) * P2 + k2];
            } else if (k == 152) {
                vals[P3 + P2] = U1[m];
            }
        }
        unsigned long long a2[KW];
#pragma unroll
        for (int kp = 0; kp < KW; kp++) a2[kp] = pack2(vals[kp], vals[kp]);

        for (int j = 0; j < 80; j += 2) {
            unsigned long long acc2 = 0ull;
#pragma unroll
            for (int kp = 0; kp < KW; kp++)
                acc2 = fma2(a2[kp], *(const unsigned long long*)&ws[kp][j], acc2);
            float g0, g1;
            unpack2(g0, g1, acc2);
            size_t ecA = (size_t)(ec0 + j), ecB = ecA + 1;
            __nv_bfloat16 h0 = __float2bfloat16(g0);
            __nv_bfloat16 h1 = __float2bfloat16(g1);
            g_Ghi[ecA * GSZ + o] = h0;
            g_Glo[ecA * GSZ + o] = __float2bfloat16(g0 - __bfloat162float(h0));
            g_Ghi[ecB * GSZ + o] = h1;
            g_Glo[ecB * GSZ + o] = __float2bfloat16(g1 - __bfloat162float(h1));
        }
        return;
    }

    // ---- zbuild: warp per (b,c) row ----
    {
        int rc = (bx - 1 - BG_CTAS) * 8 + (tid >> 5);
        int lane = tid & 31;
        float xv = (lane < ELL) ? x[(size_t)rc * ELL + lane] : 0.f;
        uint32_t* zrow = g_Z + (size_t)rc * ZROW;
#pragma unroll
        for (int it = 0; it < 3; it++) {
            int kk = lane + 32 * it;
            int v0, i0, v1, i1;
            if (kk < 64) {
                int d = kk >> 3;
                v0 = (kk & 7) * 2;
                i0 = (v0 + d) & 15;
                v1 = v0 + 1;
                i1 = (v0 + 1 + d) & 15;
            } else if (kk < 68) {
                v0 = (kk - 64) * 2;
                i0 = v0 + 8;
                v1 = v0 + 1;
                i1 = v0 + 9;
            } else if (kk < 76) {
                v0 = (kk - 68) * 2;
                i0 = 0;
                v1 = v0 + 1;
                i1 = 0;
            } else {
                v0 = i0 = v1 = i1 = 0;
            }
            float xa0 = __shfl_sync(0xffffffffu, xv, v0);
            float xb0 = __shfl_sync(0xffffffffu, xv, i0);
            float xa1 = __shfl_sync(0xffffffffu, xv, v1);
            float xb1 = __shfl_sync(0xffffffffu, xv, i1);
            float z0 = (kk < 68) ? xa0 * xb0 : (kk < 76 ? xa0 : (kk == 76 ? 1.f : 0.f));
            float z1 = (kk < 68) ? xa1 * xb1 : (kk < 76 ? xa1 : 0.f);
            if (kk < KPAIR) {
                uint32_t lo;
                uint32_t hi = tsplit(z0, z1, lo);
                int g = kk >> 2, w = kk & 3;
                zrow[g * 8 + w] = hi;
                zrow[g * 8 + 4 + w] = lo;
            }
        }
    }
}

// ---------------------------------------------------------------------------
// Kernel C: per (e,c) CTA, 192 threads, 3 CTAs/SM, NT=32, double-buffered
// cp.async Z gather + async A stage, all overlapped with GEMM.
// ---------------------------------------------------------------------------
#define LDSM4(D0, D1, D2, D3, ADDR)                                         \
    asm volatile("ldmatrix.sync.aligned.m8n8.x4.shared.b16 {%0,%1,%2,%3}, [%4];" \
                 : "=r"(D0), "=r"(D1), "=r"(D2), "=r"(D3) : "r"(ADDR))

#define MMA_BF16(CC, A0, A1, A2, A3, B0, B1)                                \
    asm volatile(                                                           \
        "mma.sync.aligned.m16n8k16.row.col.f32.bf16.bf16.f32 "              \
        "{%0,%1,%2,%3}, {%4,%5,%6,%7}, {%8,%9}, {%0,%1,%2,%3};"             \
        : "+f"(CC[0]), "+f"(CC[1]), "+f"(CC[2]), "+f"(CC[3])                \
        : "r"(A0), "r"(A1), "r"(A2), "r"(A3), "r"(B0), "r"(B1))

__global__ void __launch_bounds__(192, 3) contract_kernel(float* __restrict__ out) {
    int c = blockIdx.x, e = blockIdx.y;
    int ec = e * C_SZ + c;
    int t = threadIdx.x;
    int warp = t >> 5, lane = t & 31;
    int mi = warp >> 1, ni = warp & 1;
    int q = lane & 3, r = lane >> 2;

    int b0 = g_bstart[e], b1 = g_bstart[e + 1];
    if (b1 <= b0) return;
    int ntiles = (b1 - b0 + NT - 1) / NT;

    __shared__ __align__(16) uint32_t Ah[MROWS * LDA], Al[MROWS * LDA];
    __shared__ __align__(16) uint32_t Zh_s[2 * NT * LDA], Zl_s[2 * NT * LDA];
    __shared__ int border[2][NT];

    uint32_t saAh = (uint32_t)__cvta_generic_to_shared(Ah);
    uint32_t saAl = (uint32_t)__cvta_generic_to_shared(Al);
    uint32_t saZh = (uint32_t)__cvta_generic_to_shared(Zh_s);
    uint32_t saZl = (uint32_t)__cvta_generic_to_shared(Zl_s);

    // Stage A (hi+lo) asynchronously (completes with group 0).
    {
        const uint4* gh = (const uint4*)g_Ghi + (size_t)ec * (MROWS * 20);
        const uint4* gl = (const uint4*)g_Glo + (size_t)ec * (MROWS * 20);
        for (int p = t; p < MROWS * 20; p += 192) {
            int m = p / 20, j = p - m * 20;
            uint32_t dh = saAh + (uint32_t)(m * LDA + j * 4) * 4u;
            uint32_t dl = saAl + (uint32_t)(m * LDA + j * 4) * 4u;
            CP_ASYNC16(dh, (const char*)(gh + p));
            CP_ASYNC16(dl, (const char*)(gl + p));
        }
    }

    // gather one tile's Z rows into buffer `buf` via cp.async
    auto gather = [&](int ti, int buf) {
        int tb = b0 + ti * NT;
        int nbt = min(NT, b1 - tb);
        uint32_t bufoff = (uint32_t)buf * NT * LDA * 4u;
        for (int n = warp; n < nbt; n += 6) {
            int bidx = g_order[tb + n];
            if (lane == 0) border[buf][n] = bidx;
            const uint32_t* src = g_Z + ((size_t)bidx * C_SZ + c) * ZROW;
            {
                int j = lane;
                uint32_t dst = ((j & 1) ? saZl : saZh) + bufoff +
                               ((uint32_t)n * LDA + (uint32_t)(j >> 1) * 4u) * 4u;
                CP_ASYNC16(dst, (const char*)(src + j * 4));
            }
            if (lane < 8) {
                int j = 32 + lane;
                uint32_t dst = ((j & 1) ? saZl : saZh) + bufoff +
                               ((uint32_t)n * LDA + (uint32_t)(j >> 1) * 4u) * 4u;
                CP_ASYNC16(dst, (const char*)(src + j * 4));
            }
        }
    };

    // LDSM lane addresses
    int rowA = mi * 16 + (lane & 7) + ((lane >> 3) & 1) * 8;
    int colA = (lane >> 4) * 4;
    uint32_t aAh = saAh + (uint32_t)(rowA * LDA + colA) * 4u;
    uint32_t aAl = saAl + (uint32_t)(rowA * LDA + colA) * 4u;
    int rowB = ni * 8 + (lane & 7);
    int colB = (lane >> 3) * 4;
    uint32_t bOff = (uint32_t)(rowB * LDA + colB) * 4u;

    gather(0, 0);
    CP_COMMIT();   // group 0 = A stage + tile 0

    for (int ti = 0; ti < ntiles; ti++) {
        int cur = ti & 1;
        if (ti + 1 < ntiles) {
            gather(ti + 1, 1 - cur);
            CP_COMMIT();
            CP_WAIT1();
        } else {
            CP_WAIT0();
        }
        __syncthreads();

        uint32_t bufoff = (uint32_t)cur * NT * LDA * 4u;
        uint32_t aB0h = saZh + bufoff + bOff;
        uint32_t aB0l = saZl + bufoff + bOff;
        uint32_t aB1h = aB0h + 16u * LDA * 4u;
        uint32_t aB1l = aB0l + 16u * LDA * 4u;

        float acc[6][4];
#pragma unroll
        for (int s = 0; s < 6; s++)
#pragma unroll
            for (int j = 0; j < 4; j++) acc[s][j] = 0.f;

#pragma unroll
        for (int g2 = 0; g2 < 5; g2++) {
            uint32_t off2 = (uint32_t)g2 * 64u;
            uint32_t ah0, ah1, ah2, ah3, ap0, ap1, ap2, ap3;
            uint32_t al0, al1, al2, al3, aq0, aq1, aq2, aq3;
            uint32_t bh0, bh1, bh2, bh3, bl0, bl1, bl2, bl3;
            uint32_t ch0, ch1, ch2, ch3, cl0, cl1, cl2, cl3;
            LDSM4(ah0, ah1, ah2, ah3, aAh + off2);
            LDSM4(ap0, ap1, ap2, ap3, aAh + off2 + 32u);
            LDSM4(al0, al1, al2, al3, aAl + off2);
            LDSM4(aq0, aq1, aq2, aq3, aAl + off2 + 32u);
            LDSM4(bh0, bh1, bh2, bh3, aB0h + off2);
            LDSM4(bl0, bl1, bl2, bl3, aB0l + off2);
            LDSM4(ch0, ch1, ch2, ch3, aB1h + off2);
            LDSM4(cl0, cl1, cl2, cl3, aB1l + off2);
            MMA_BF16(acc[0], ah0, ah1, ah2, ah3, bh0, bh1);
            MMA_BF16(acc[1], ah0, ah1, ah2, ah3, bl0, bl1);
            MMA_BF16(acc[2], al0, al1, al2, al3, bh0, bh1);
            MMA_BF16(acc[3], ah0, ah1, ah2, ah3, ch0, ch1);
            MMA_BF16(acc[4], ah0, ah1, ah2, ah3, cl0, cl1);
            MMA_BF16(acc[5], al0, al1, al2, al3, ch0, ch1);
            MMA_BF16(acc[0], ap0, ap1, ap2, ap3, bh2, bh3);
            MMA_BF16(acc[1], ap0, ap1, ap2, ap3, bl2, bl3);
            MMA_BF16(acc[2], aq0, aq1, aq2, aq3, bh2, bh3);
            MMA_BF16(acc[3], ap0, ap1, ap2, ap3, ch2, ch3);
            MMA_BF16(acc[4], ap0, ap1, ap2, ap3, cl2, cl3);
            MMA_BF16(acc[5], aq0, aq1, aq2, aq3, ch2, ch3);
        }

        // x reconstruction from Z linear block: pair p = 68 + (idx>>1)
        auto xval = [&](int n, int idx) -> float {
            int p = 68 + (idx >> 1);
            uint32_t h = Zh_s[cur * NT * LDA + n * LDA + p];
            uint32_t l = Zl_s[cur * NT * LDA + n * LDA + p];
            uint32_t hs = (idx & 1) ? (h & 0xFFFF0000u) : (h << 16);
            uint32_t ls = (idx & 1) ? (l & 0xFFFF0000u) : (l << 16);
            return __uint_as_float(hs) + __uint_as_float(ls);
        };

        int tb = b0 + ti * NT;
        int nb = min(NT, b1 - tb);
#pragma unroll
        for (int f = 0; f < 2; f++) {
            float c0 = acc[3 * f][0] + acc[3 * f + 1][0] + acc[3 * f + 2][0];
            float c1 = acc[3 * f][1] + acc[3 * f + 1][1] + acc[3 * f + 2][1];
            float c2 = acc[3 * f][2] + acc[3 * f + 1][2] + acc[3 * f + 2][2];
            float c3 = acc[3 * f][3] + acc[3 * f + 1][3] + acc[3 * f + 2][3];
            int bc0 = f * 16 + ni * 8 + 2 * q;
            int bc1 = bc0 + 1;
            float p0 = c0 * xval(bc0, r) + c2 * xval(bc0, r + 8);
            float p1 = c1 * xval(bc1, r) + c3 * xval(bc1, r + 8);
#pragma unroll
            for (int off = 4; off <= 16; off <<= 1) {
                p0 += __shfl_xor_sync(0xffffffffu, p0, off);
                p1 += __shfl_xor_sync(0xffffffffu, p1, off);
            }
            if (lane < 4) {
                if (bc0 < nb) out[(size_t)border[cur][bc0] * OUT_STRIDE + c * EQ + mi] = p0;
                if (bc1 < nb) out[(size_t)border[cur][bc1] * OUT_STRIDE + c * EQ + mi] = p1;
            }
        }
        __syncthreads();
    }
}

// ---------------------------------------------------------------------------
extern "C" void kernel_launch(void* const* d_in, const int* in_sizes, int n_in,
                              void* d_out, int out_size) {
    const float* x    = (const float*)d_in[0];
    const float* y    = (const float*)d_in[1];
    const float* U3   = (const float*)d_in[2];
    const float* U2   = (const float*)d_in[3];
    const float* U1   = (const float*)d_in[4];
    const float* wmax = (const float*)d_in[5];
    const float* w2   = (const float*)d_in[6];
    const float* w1   = (const float*)d_in[7];
    float* out = (float*)d_out;

    mega_kernel<<<1 + BG_CTAS + ZB_CTAS, 256>>>(x, y, U3, U2, U1, wmax, w2, w1);
    contract_kernel<<<dim3(C_SZ, E_SZ), 192>>>(out);
}